// round 2
// baseline (speedup 1.0000x reference)
#include <cuda_runtime.h>
#include <cuda_bf16.h>
#include <cstdint>

// Problem constants
#define TSEQ 1024
#define BATCH 64
#define HID 128
#define G4 512            // 4*HID
#define XGHALF (TSEQ*BATCH*G4)   // per-direction xg elements

// ---------------- scratch (static device globals; no allocations) -------------
__device__ float g_xt[TSEQ * BATCH * 128];        // x transposed to [T,B,128]
__device__ float g_xg[2 * TSEQ * BATCH * G4];     // [dir][T][B][512]
__device__ float g_out1[TSEQ * BATCH * 256];      // layer-1 output [T,B,256]

// ---------------- fast activations -------------------------------------------
__device__ __forceinline__ float fsig(float x) {
    return 1.0f / (1.0f + __expf(-x));
}
__device__ __forceinline__ float ftanh_(float x) {
    return 2.0f * fsig(2.0f * x) - 1.0f;
}

// ---------------- transpose x: [B,T,128] -> [T,B,128] -------------------------
__global__ void transpose_x(const float4* __restrict__ x, float4* __restrict__ xt) {
    int i = blockIdx.x * blockDim.x + threadIdx.x;   // over T*B*32 float4s
    if (i >= TSEQ * BATCH * 32) return;
    int t  = i >> 11;          // / (64*32)
    int r  = i & 2047;
    int b  = r >> 5;
    int k4 = r & 31;
    xt[i] = x[((size_t)b * TSEQ + t) * 32 + k4];
}

// ---------------- SGEMM: C[M,N] = A[M,K] * B[N,K]^T + bias1[n] + bias2[n] -----
// BM=64, BN=64, BK=16, 256 threads, 4x4 per thread. M%64==0, N%64==0, K%16==0.
#define BM 64
#define BN 64
#define BKK 16
__global__ __launch_bounds__(256) void sgemm_bias(
    const float* __restrict__ A, const float* __restrict__ B,
    const float* __restrict__ bias1, const float* __restrict__ bias2,
    float* __restrict__ C, int M, int N, int K)
{
    __shared__ float As[BKK][BM + 4];
    __shared__ float Bs[BKK][BN + 4];

    int tid = threadIdx.x;
    int tx = tid & 15;       // 0..15
    int ty = tid >> 4;       // 0..15
    int block_m = blockIdx.x * BM;
    int block_n = blockIdx.y * BN;

    int lr = tid >> 2;               // 0..63 load row
    int lc = (tid & 3) * 4;          // 0,4,8,12 load col (k)

    const float* Ab = A + (size_t)(block_m + lr) * K + lc;
    const float* Bb = B + (size_t)(block_n + lr) * K + lc;

    float acc[4][4];
#pragma unroll
    for (int i = 0; i < 4; i++)
#pragma unroll
        for (int jj = 0; jj < 4; jj++) acc[i][jj] = 0.f;

    for (int k0 = 0; k0 < K; k0 += BKK) {
        float4 av = *(const float4*)(Ab + k0);
        float4 bv = *(const float4*)(Bb + k0);
        As[lc + 0][lr] = av.x; As[lc + 1][lr] = av.y;
        As[lc + 2][lr] = av.z; As[lc + 3][lr] = av.w;
        Bs[lc + 0][lr] = bv.x; Bs[lc + 1][lr] = bv.y;
        Bs[lc + 2][lr] = bv.z; Bs[lc + 3][lr] = bv.w;
        __syncthreads();
#pragma unroll
        for (int k = 0; k < BKK; k++) {
            float4 a = *(const float4*)&As[k][ty * 4];
            float4 b = *(const float4*)&Bs[k][tx * 4];
            acc[0][0] += a.x * b.x; acc[0][1] += a.x * b.y;
            acc[0][2] += a.x * b.z; acc[0][3] += a.x * b.w;
            acc[1][0] += a.y * b.x; acc[1][1] += a.y * b.y;
            acc[1][2] += a.y * b.z; acc[1][3] += a.y * b.w;
            acc[2][0] += a.z * b.x; acc[2][1] += a.z * b.y;
            acc[2][2] += a.z * b.z; acc[2][3] += a.z * b.w;
            acc[3][0] += a.w * b.x; acc[3][1] += a.w * b.y;
            acc[3][2] += a.w * b.z; acc[3][3] += a.w * b.w;
        }
        __syncthreads();
    }

#pragma unroll
    for (int i = 0; i < 4; i++) {
        size_t row = (size_t)(block_m + ty * 4 + i);
#pragma unroll
        for (int jj = 0; jj < 4; jj++) {
            int n = block_n + tx * 4 + jj;
            C[row * N + n] = acc[i][jj] + __ldg(&bias1[n]) + __ldg(&bias2[n]);
        }
    }
}

// ---------------- recurrent LSTM scan: one CTA per (batch, direction) ---------
// 512 threads; thread j owns gate row j (gate = j>>7 in {i,f,g,o}).
// Whh row j: first RK cols in registers, remaining in smem (transposed [k][j]).
#define RK 64
#define REC_SMEM_FLOATS ((128 - RK) * G4 + HID + G4)
#define REC_SMEM_BYTES (REC_SMEM_FLOATS * 4)

__global__ __launch_bounds__(512, 1) void lstm_rec(
    const float* __restrict__ xg,        // [dir][T][B][512]
    const float* __restrict__ Whh0,      // fw weights [512][128]
    const float* __restrict__ Whh1,      // bw weights [512][128]
    float* __restrict__ out,             // h output
    int outT, int outB)                  // strides (floats) for t and b
{
    extern __shared__ float sm[];
    float* ws = sm;                              // (128-RK)*512
    float* hs = sm + (128 - RK) * G4;            // 128
    float* gs = hs + HID;                        // 512

    int j   = threadIdx.x;
    int b   = blockIdx.x;
    int dir = blockIdx.y;
    const float* Whh = dir ? Whh1 : Whh0;

    // load per-thread register weights (cols 0..RK-1 of row j)
    float w[RK];
    const float4* Wr4 = (const float4*)(Whh + (size_t)j * 128);
#pragma unroll
    for (int k4 = 0; k4 < RK / 4; k4++) {
        float4 v = Wr4[k4];
        w[4 * k4 + 0] = v.x; w[4 * k4 + 1] = v.y;
        w[4 * k4 + 2] = v.z; w[4 * k4 + 3] = v.w;
    }
    // stage cols RK..127 of row j into smem, transposed: ws[(k-RK)*512 + j]
#pragma unroll
    for (int k4 = RK / 4; k4 < 32; k4++) {
        float4 v = Wr4[k4];
        int base = (k4 * 4 - RK) * G4 + j;
        ws[base + 0 * G4] = v.x; ws[base + 1 * G4] = v.y;
        ws[base + 2 * G4] = v.z; ws[base + 3 * G4] = v.w;
    }
    if (j < HID) hs[j] = 0.f;
    float c = 0.f;
    __syncthreads();

    const float4* hs4 = (const float4*)hs;
    size_t xg_base = (size_t)dir * XGHALF + (size_t)b * G4 + j;
    int t0 = dir ? (TSEQ - 1) : 0;
    float xgv = __ldg(xg + xg_base + (size_t)t0 * (BATCH * G4));
    float* outp = out + dir * HID;

    for (int s = 0; s < TSEQ; s++) {
        int t = dir ? (TSEQ - 1 - s) : s;
        // prefetch next timestep's xg (hidden under the dot product)
        float xgn = 0.f;
        if (s + 1 < TSEQ) {
            int tn = dir ? (t - 1) : (t + 1);
            xgn = __ldg(xg + xg_base + (size_t)tn * (BATCH * G4));
        }

        float a0 = xgv, a1 = 0.f, a2 = 0.f, a3 = 0.f;
#pragma unroll
        for (int kk = 0; kk < RK / 4; kk++) {
            float4 hv = hs4[kk];
            a0 += w[4 * kk + 0] * hv.x;
            a1 += w[4 * kk + 1] * hv.y;
            a2 += w[4 * kk + 2] * hv.z;
            a3 += w[4 * kk + 3] * hv.w;
        }
#pragma unroll
        for (int kk = 0; kk < (128 - RK) / 4; kk++) {
            float4 hv = hs4[RK / 4 + kk];
            int base = (4 * kk) * G4 + j;
            a0 += ws[base + 0 * G4] * hv.x;
            a1 += ws[base + 1 * G4] * hv.y;
            a2 += ws[base + 2 * G4] * hv.z;
            a3 += ws[base + 3 * G4] * hv.w;
        }
        float pre = (a0 + a1) + (a2 + a3);

        int gate = j >> 7;                       // 0:i 1:f 2:g 3:o
        float v = (gate == 2) ? ftanh_(pre) : fsig(pre);
        gs[j] = v;
        __syncthreads();

        if (j < HID) {
            float iv = gs[j];
            float fv = gs[j + HID];
            float gv = gs[j + 2 * HID];
            float ov = gs[j + 3 * HID];
            c = fv * c + iv * gv;
            float h = ov * ftanh_(c);
            hs[j] = h;
            outp[(size_t)t * outT + (size_t)b * outB + j] = h;
        }
        __syncthreads();
        xgv = xgn;
    }
}

// ---------------- launch ------------------------------------------------------
extern "C" void kernel_launch(void* const* d_in, const int* in_sizes, int n_in,
                              void* d_out, int out_size)
{
    const float* x        = (const float*)d_in[0];
    // d_in[1] = lengths (unused, as in the reference)
    const float* Wih_fw1  = (const float*)d_in[2];
    const float* Whh_fw1  = (const float*)d_in[3];
    const float* bih_fw1  = (const float*)d_in[4];
    const float* bhh_fw1  = (const float*)d_in[5];
    const float* Wih_bw1  = (const float*)d_in[6];
    const float* Whh_bw1  = (const float*)d_in[7];
    const float* bih_bw1  = (const float*)d_in[8];
    const float* bhh_bw1  = (const float*)d_in[9];
    const float* Wih_fw2  = (const float*)d_in[10];
    const float* Whh_fw2  = (const float*)d_in[11];
    const float* bih_fw2  = (const float*)d_in[12];
    const float* bhh_fw2  = (const float*)d_in[13];
    const float* Wih_bw2  = (const float*)d_in[14];
    const float* Whh_bw2  = (const float*)d_in[15];
    const float* bih_bw2  = (const float*)d_in[16];
    const float* bhh_bw2  = (const float*)d_in[17];
    float* out = (float*)d_out;

    float *xt, *xg, *out1;
    cudaGetSymbolAddress((void**)&xt,   g_xt);
    cudaGetSymbolAddress((void**)&xg,   g_xg);
    cudaGetSymbolAddress((void**)&out1, g_out1);

    cudaFuncSetAttribute(lstm_rec, cudaFuncAttributeMaxDynamicSharedMemorySize,
                         REC_SMEM_BYTES);

    const int M = TSEQ * BATCH;          // 65536

    // 1) transpose x -> [T,B,128]
    transpose_x<<<(TSEQ * BATCH * 32 + 255) / 256, 256>>>(
        (const float4*)x, (float4*)xt);

    // 2) layer-1 input projections (bias = bih + bhh folded in)
    dim3 gg(M / BM, G4 / BN);
    sgemm_bias<<<gg, 256>>>(xt, Wih_fw1, bih_fw1, bhh_fw1, xg,          M, G4, 128);
    sgemm_bias<<<gg, 256>>>(xt, Wih_bw1, bih_bw1, bhh_bw1, xg + XGHALF, M, G4, 128);

    // 3) layer-1 recurrence -> out1 [T,B,256]
    lstm_rec<<<dim3(BATCH, 2), 512, REC_SMEM_BYTES>>>(
        xg, Whh_fw1, Whh_bw1, out1, BATCH * 256, 256);

    // 4) layer-2 input projections (K = 256)
    sgemm_bias<<<gg, 256>>>(out1, Wih_fw2, bih_fw2, bhh_fw2, xg,          M, G4, 256);
    sgemm_bias<<<gg, 256>>>(out1, Wih_bw2, bih_bw2, bhh_bw2, xg + XGHALF, M, G4, 256);

    // 5) layer-2 recurrence -> d_out [B,T,256]
    lstm_rec<<<dim3(BATCH, 2), 512, REC_SMEM_BYTES>>>(
        xg, Whh_fw2, Whh_bw2, out, 256, TSEQ * 256);
}